// round 1
// baseline (speedup 1.0000x reference)
#include <cuda_runtime.h>
#include <math.h>

#define NB 4
#define CC 256
#define HWD 4096
#define NH 4
#define HD 64
#define NGRP 8
#define GC 32          // channels per group
#define EPSV 1e-5f
#define LOG2E 1.44269504088896340736f

// ---- scratch (allocation-free: __device__ globals) ----
__device__ float g_q[NB * CC * HWD];   // [n][c][hw], pre-scaled by hd^-0.5 * log2(e)
__device__ float g_k[NB * CC * HWD];   // [n][c][hw]
__device__ float g_v[NB * CC * HWD];   // [n][c][hw]
__device__ float g_ao[NB * CC * HWD];  // attention output, [n][c][hw]
__device__ float g_mean[NB * NGRP];
__device__ float g_rstd[NB * NGRP];

// ---------------------------------------------------------------------------
// GroupNorm statistics: one block per (n, group); reduce 32ch x 4096 elems.
// ---------------------------------------------------------------------------
__global__ void gn_stats_kernel(const float* __restrict__ x) {
    int ng = blockIdx.x;  // n*NGRP + g ; channels contiguous -> base = ng*GC*HWD
    const float4* xp = (const float4*)(x + (size_t)ng * GC * HWD);
    const int nvec = GC * HWD / 4;  // 32768
    float s = 0.f, ss = 0.f;
    for (int i = threadIdx.x; i < nvec; i += blockDim.x) {
        float4 v = xp[i];
        s  += v.x + v.y + v.z + v.w;
        ss += v.x * v.x + v.y * v.y + v.z * v.z + v.w * v.w;
    }
    __shared__ float sh[512];
    sh[threadIdx.x] = s;
    sh[256 + threadIdx.x] = ss;
    __syncthreads();
    for (int st = 128; st > 0; st >>= 1) {
        if (threadIdx.x < st) {
            sh[threadIdx.x]       += sh[threadIdx.x + st];
            sh[256 + threadIdx.x] += sh[256 + threadIdx.x + st];
        }
        __syncthreads();
    }
    if (threadIdx.x == 0) {
        const float inv = 1.0f / (float)(GC * HWD);
        float m   = sh[0] * inv;
        float var = sh[256] * inv - m * m;
        g_mean[ng] = m;
        g_rstd[ng] = rsqrtf(var + EPSV);
    }
}

// ---------------------------------------------------------------------------
// QKV GEMM with GroupNorm affine fused into the B-tile load.
// C[o][hw] = sum_c W[o][c] * xn[c][hw] + b[o]
// Tile 64(M=o) x 64(N=hw), K-chunk 16, 256 threads, 4x4 microtile.
// Epilogue routes into g_q / g_k / g_v (q scaled by hd^-0.5 * log2e).
// ---------------------------------------------------------------------------
__global__ __launch_bounds__(256) void qkv_gemm_kernel(
    const float* __restrict__ x,
    const float* __restrict__ norm_w, const float* __restrict__ norm_b,
    const float* __restrict__ qkv_w,  const float* __restrict__ qkv_b)
{
    const int n  = blockIdx.z;
    const int o0 = blockIdx.y * 64;
    const int j0 = blockIdx.x * 64;
    __shared__ __align__(16) float As[16][64];
    __shared__ __align__(16) float Bs[16][64];
    __shared__ float sc[CC], bc[CC];

    const int t  = threadIdx.x;
    const int tx = t & 15, ty = t >> 4;

    // per-channel GN affine: xn = x*sc + bc
    {
        int c = t;  // 256 threads, 256 channels
        int g = c / GC;
        float rs = g_rstd[n * NGRP + g];
        float mn = g_mean[n * NGRP + g];
        float s  = rs * norm_w[c];
        sc[c] = s;
        bc[c] = norm_b[c] - mn * s;
    }
    __syncthreads();

    float acc[4][4] = {};
    const float* xb = x + (size_t)n * CC * HWD;

    for (int k0 = 0; k0 < CC; k0 += 16) {
        {   // A tile: 64 rows(o) x 16(k)
            int m  = t & 63;
            int kb = (t >> 6) * 4;
            float4 a4 = *(const float4*)(qkv_w + (size_t)(o0 + m) * CC + k0 + kb);
            As[kb + 0][m] = a4.x; As[kb + 1][m] = a4.y;
            As[kb + 2][m] = a4.z; As[kb + 3][m] = a4.w;
        }
        {   // B tile: 16(k) x 64(hw), normalized on the fly
            int j  = t & 63;
            int kr = t >> 6;
            #pragma unroll
            for (int r = 0; r < 4; r++) {
                int k = kr + r * 4;
                int c = k0 + k;
                Bs[k][j] = xb[(size_t)c * HWD + j0 + j] * sc[c] + bc[c];
            }
        }
        __syncthreads();
        #pragma unroll
        for (int kk = 0; kk < 16; kk++) {
            float4 a4 = *(const float4*)&As[kk][ty * 4];
            float4 b4 = *(const float4*)&Bs[kk][tx * 4];
            float a[4] = {a4.x, a4.y, a4.z, a4.w};
            float b[4] = {b4.x, b4.y, b4.z, b4.w};
            #pragma unroll
            for (int i = 0; i < 4; i++)
                #pragma unroll
                for (int j = 0; j < 4; j++)
                    acc[i][j] += a[i] * b[j];
        }
        __syncthreads();
    }

    // epilogue: route to q/k/v, coalesced float4 stores
    #pragma unroll
    for (int i = 0; i < 4; i++) {
        int o    = o0 + ty * 4 + i;
        int part = o >> 8;       // 0=q,1=k,2=v  (o-tile of 64 never straddles)
        int c    = o & 255;
        float bias  = qkv_b[o];
        float scale = (part == 0) ? (0.125f * LOG2E) : 1.0f;
        float* dst  = (part == 0) ? g_q : ((part == 1) ? g_k : g_v);
        float4 r;
        r.x = (acc[i][0] + bias) * scale;
        r.y = (acc[i][1] + bias) * scale;
        r.z = (acc[i][2] + bias) * scale;
        r.w = (acc[i][3] + bias) * scale;
        *(float4*)(dst + (size_t)n * CC * HWD + (size_t)c * HWD + j0 + tx * 4) = r;
    }
}

// ---------------------------------------------------------------------------
// Flash-style attention. One thread per query row (128 q / block).
// K/V streamed in tiles of 32 keys through smem, stored [d][j] so
//   - gmem loads coalesced (lane = j),
//   - smem writes conflict-free,
//   - compute reads warp-uniform (broadcast) float4.
// q already holds hd^-0.5 * log2e scaling -> softmax via exp2f.
// ---------------------------------------------------------------------------
__global__ __launch_bounds__(128) void attn_kernel() {
    const int nh = blockIdx.y;            // n*NH + h
    const int n  = nh / NH, h = nh % NH;
    const int i  = blockIdx.x * 128 + threadIdx.x;  // query index

    const float* qb = g_q + (size_t)n * CC * HWD + (size_t)h * HD * HWD;
    const float* kb = g_k + (size_t)n * CC * HWD + (size_t)h * HD * HWD;
    const float* vb = g_v + (size_t)n * CC * HWD + (size_t)h * HD * HWD;

    float q[HD];
    #pragma unroll
    for (int d = 0; d < HD; d++) q[d] = qb[(size_t)d * HWD + i];  // coalesced per d

    float acc[HD];
    #pragma unroll
    for (int d = 0; d < HD; d++) acc[d] = 0.f;
    float mcur = -INFINITY, l = 0.f;

    __shared__ __align__(16) float Ks[HD][32];
    __shared__ __align__(16) float Vs[HD][32];
    const int lane = threadIdx.x & 31, wrp = threadIdx.x >> 5;

    for (int j0 = 0; j0 < HWD; j0 += 32) {
        __syncthreads();
        #pragma unroll
        for (int r = 0; r < 16; r++) {
            int d = wrp * 16 + r;
            Ks[d][lane] = kb[(size_t)d * HWD + j0 + lane];
            Vs[d][lane] = vb[(size_t)d * HWD + j0 + lane];
        }
        __syncthreads();

        // scores
        float s[32];
        #pragma unroll
        for (int jj = 0; jj < 32; jj++) s[jj] = 0.f;
        #pragma unroll
        for (int d = 0; d < HD; d++) {
            float qd = q[d];
            #pragma unroll
            for (int jj = 0; jj < 8; jj++) {
                float4 k4 = *(const float4*)&Ks[d][jj * 4];
                s[jj * 4 + 0] += qd * k4.x;
                s[jj * 4 + 1] += qd * k4.y;
                s[jj * 4 + 2] += qd * k4.z;
                s[jj * 4 + 3] += qd * k4.w;
            }
        }

        // online softmax update (log2 domain)
        float tmax = s[0];
        #pragma unroll
        for (int jj = 1; jj < 32; jj++) tmax = fmaxf(tmax, s[jj]);
        float mnew = fmaxf(mcur, tmax);
        float corr = exp2f(mcur - mnew);
        mcur = mnew;
        float lsum = 0.f;
        #pragma unroll
        for (int jj = 0; jj < 32; jj++) { s[jj] = exp2f(s[jj] - mnew); lsum += s[jj]; }
        l = l * corr + lsum;
        #pragma unroll
        for (int d = 0; d < HD; d++) acc[d] *= corr;

        // acc += P @ V
        #pragma unroll
        for (int d = 0; d < HD; d++) {
            float a = acc[d];
            #pragma unroll
            for (int jj = 0; jj < 8; jj++) {
                float4 v4 = *(const float4*)&Vs[d][jj * 4];
                a += s[jj * 4 + 0] * v4.x;
                a += s[jj * 4 + 1] * v4.y;
                a += s[jj * 4 + 2] * v4.z;
                a += s[jj * 4 + 3] * v4.w;
            }
            acc[d] = a;
        }
    }

    float inv = 1.0f / l;
    float* ob = g_ao + (size_t)n * CC * HWD + (size_t)h * HD * HWD;
    #pragma unroll
    for (int d = 0; d < HD; d++)
        ob[(size_t)d * HWD + i] = acc[d] * inv;  // coalesced per d
}

// ---------------------------------------------------------------------------
// Projection GEMM + bias + residual + mask. Same tiling as QKV GEMM.
// ---------------------------------------------------------------------------
__global__ __launch_bounds__(256) void proj_gemm_kernel(
    const float* __restrict__ x, const float* __restrict__ mask,
    const float* __restrict__ pw, const float* __restrict__ pb,
    float* __restrict__ out)
{
    const int n  = blockIdx.z;
    const int o0 = blockIdx.y * 64;
    const int j0 = blockIdx.x * 64;
    __shared__ __align__(16) float As[16][64];
    __shared__ __align__(16) float Bs[16][64];
    const int t  = threadIdx.x;
    const int tx = t & 15, ty = t >> 4;

    float acc[4][4] = {};
    const float* Bb = g_ao + (size_t)n * CC * HWD;

    for (int k0 = 0; k0 < CC; k0 += 16) {
        {
            int m  = t & 63;
            int kb = (t >> 6) * 4;
            float4 a4 = *(const float4*)(pw + (size_t)(o0 + m) * CC + k0 + kb);
            As[kb + 0][m] = a4.x; As[kb + 1][m] = a4.y;
            As[kb + 2][m] = a4.z; As[kb + 3][m] = a4.w;
        }
        {
            int j  = t & 63;
            int kr = t >> 6;
            #pragma unroll
            for (int r = 0; r < 4; r++) {
                int k = kr + r * 4;
                Bs[k][j] = Bb[(size_t)(k0 + k) * HWD + j0 + j];
            }
        }
        __syncthreads();
        #pragma unroll
        for (int kk = 0; kk < 16; kk++) {
            float4 a4 = *(const float4*)&As[kk][ty * 4];
            float4 b4 = *(const float4*)&Bs[kk][tx * 4];
            float a[4] = {a4.x, a4.y, a4.z, a4.w};
            float b[4] = {b4.x, b4.y, b4.z, b4.w};
            #pragma unroll
            for (int i = 0; i < 4; i++)
                #pragma unroll
                for (int j = 0; j < 4; j++)
                    acc[i][j] += a[i] * b[j];
        }
        __syncthreads();
    }

    float4 mv = *(const float4*)(mask + (size_t)n * HWD + j0 + tx * 4);
    #pragma unroll
    for (int i = 0; i < 4; i++) {
        int o = o0 + ty * 4 + i;
        float bias = pb[o];
        size_t off = (size_t)n * CC * HWD + (size_t)o * HWD + j0 + tx * 4;
        float4 xv = *(const float4*)(x + off);
        float4 r;
        r.x = (xv.x + acc[i][0] + bias) * mv.x;
        r.y = (xv.y + acc[i][1] + bias) * mv.y;
        r.z = (xv.z + acc[i][2] + bias) * mv.z;
        r.w = (xv.w + acc[i][3] + bias) * mv.w;
        *(float4*)(out + off) = r;
    }
}

__global__ void copy_mask_kernel(const float* __restrict__ mask, float* __restrict__ out) {
    int i = blockIdx.x * blockDim.x + threadIdx.x;
    if (i < NB * HWD) out[i] = mask[i];
}

// ---------------------------------------------------------------------------
extern "C" void kernel_launch(void* const* d_in, const int* in_sizes, int n_in,
                              void* d_out, int out_size) {
    const float* x      = (const float*)d_in[0];
    const float* mask   = (const float*)d_in[1];
    const float* norm_w = (const float*)d_in[2];
    const float* norm_b = (const float*)d_in[3];
    const float* qkv_w  = (const float*)d_in[4];
    const float* qkv_b  = (const float*)d_in[5];
    const float* proj_w = (const float*)d_in[6];
    const float* proj_b = (const float*)d_in[7];
    float* out = (float*)d_out;

    gn_stats_kernel<<<NB * NGRP, 256>>>(x);
    qkv_gemm_kernel<<<dim3(HWD / 64, (3 * CC) / 64, NB), 256>>>(x, norm_w, norm_b, qkv_w, qkv_b);
    attn_kernel<<<dim3(HWD / 128, NB * NH), 128>>>();
    proj_gemm_kernel<<<dim3(HWD / 64, CC / 64, NB), 256>>>(x, mask, proj_w, proj_b, out);
    if (out_size >= NB * CC * HWD + NB * HWD)
        copy_mask_kernel<<<(NB * HWD) / 256, 256>>>(mask, out + (size_t)NB * CC * HWD);
}

// round 2
// speedup vs baseline: 4.7383x; 4.7383x over previous
#include <cuda_runtime.h>
#include <cuda_fp16.h>
#include <math.h>
#include <stdint.h>

#define NB 4
#define CC 256
#define HWD 4096
#define NH 4
#define HD 64
#define NGRP 8
#define GC 32
#define EPSV 1e-5f
#define LOG2E 1.44269504088896340736f

// ---- scratch (allocation-free) ----
__device__ __half g_q16[NB * CC * HWD];   // [n][c][hw], pre-scaled by hd^-0.5*log2e
__device__ __half g_k16[NB * CC * HWD];   // [n][c][hw]
__device__ __half g_v16[NB * CC * HWD];   // [n][c][hw]
__device__ float  g_ao [NB * CC * HWD];   // attention out [n][c][hw] fp32
__device__ float  g_part[256 * 2];
__device__ float  g_mean[NB * NGRP];
__device__ float  g_rstd[NB * NGRP];

// ---------------- helpers ----------------
__device__ __forceinline__ float ex2(float x) {
    float y; asm("ex2.approx.ftz.f32 %0, %1;" : "=f"(y) : "f"(x)); return y;
}
__device__ __forceinline__ uint32_t pack2(float a, float b) {
    __half2 h = __floats2half2_rn(a, b);
    return *reinterpret_cast<uint32_t*>(&h);
}
__device__ __forceinline__ uint32_t sptr(const void* p) {
    return (uint32_t)__cvta_generic_to_shared(p);
}
__device__ __forceinline__ void cp16(void* dst, const void* src) {
    asm volatile("cp.async.cg.shared.global [%0], [%1], 16;\n"
                 :: "r"(sptr(dst)), "l"(src));
}
__device__ __forceinline__ void ldsm4t(uint32_t* f, const void* p) {
    asm volatile("ldmatrix.sync.aligned.m8n8.x4.trans.shared.b16 {%0,%1,%2,%3}, [%4];\n"
                 : "=r"(f[0]), "=r"(f[1]), "=r"(f[2]), "=r"(f[3]) : "r"(sptr(p)));
}
__device__ __forceinline__ void ldsm4(uint32_t* f, const void* p) {
    asm volatile("ldmatrix.sync.aligned.m8n8.x4.shared.b16 {%0,%1,%2,%3}, [%4];\n"
                 : "=r"(f[0]), "=r"(f[1]), "=r"(f[2]), "=r"(f[3]) : "r"(sptr(p)));
}
__device__ __forceinline__ void mma16816(float* c, const uint32_t* a, uint32_t b0, uint32_t b1) {
    asm volatile(
        "mma.sync.aligned.m16n8k16.row.col.f32.f16.f16.f32 "
        "{%0,%1,%2,%3}, {%4,%5,%6,%7}, {%8,%9}, {%0,%1,%2,%3};\n"
        : "+f"(c[0]), "+f"(c[1]), "+f"(c[2]), "+f"(c[3])
        : "r"(a[0]), "r"(a[1]), "r"(a[2]), "r"(a[3]), "r"(b0), "r"(b1));
}

// ---------------- GroupNorm stats, 2-stage ----------------
__global__ void gn_part_kernel(const float* __restrict__ x) {
    int ng = blockIdx.x >> 3, part = blockIdx.x & 7;
    const float4* xp = (const float4*)(x + (size_t)ng * GC * HWD);
    float s = 0.f, ss = 0.f;
    int i0 = part * 4096;
    for (int i = i0 + threadIdx.x; i < i0 + 4096; i += 256) {
        float4 v = xp[i];
        s  += v.x + v.y + v.z + v.w;
        ss += v.x * v.x + v.y * v.y + v.z * v.z + v.w * v.w;
    }
    #pragma unroll
    for (int off = 16; off; off >>= 1) {
        s  += __shfl_down_sync(0xffffffffu, s, off);
        ss += __shfl_down_sync(0xffffffffu, ss, off);
    }
    __shared__ float sh[16];
    int w = threadIdx.x >> 5;
    if ((threadIdx.x & 31) == 0) { sh[w] = s; sh[8 + w] = ss; }
    __syncthreads();
    if (threadIdx.x == 0) {
        float S = 0.f, SS = 0.f;
        #pragma unroll
        for (int i = 0; i < 8; i++) { S += sh[i]; SS += sh[8 + i]; }
        g_part[blockIdx.x * 2] = S; g_part[blockIdx.x * 2 + 1] = SS;
    }
}
__global__ void gn_final_kernel() {
    int ng = threadIdx.x;
    if (ng < NB * NGRP) {
        float s = 0.f, ss = 0.f;
        #pragma unroll
        for (int p = 0; p < 8; p++) {
            s  += g_part[(ng * 8 + p) * 2];
            ss += g_part[(ng * 8 + p) * 2 + 1];
        }
        const float inv = 1.0f / (float)(GC * HWD);
        float m = s * inv;
        g_mean[ng] = m;
        g_rstd[ng] = rsqrtf(ss * inv - m * m + EPSV);
    }
}

// ---------------- QKV GEMM (fp32 math, fp16 outputs) ----------------
__global__ __launch_bounds__(256) void qkv_gemm_kernel(
    const float* __restrict__ x,
    const float* __restrict__ norm_w, const float* __restrict__ norm_b,
    const float* __restrict__ qkv_w,  const float* __restrict__ qkv_b)
{
    const int n  = blockIdx.z;
    const int o0 = blockIdx.y * 64;
    const int j0 = blockIdx.x * 64;
    __shared__ __align__(16) float As[16][64];
    __shared__ __align__(16) float Bs[16][64];
    __shared__ float sc[CC], bc[CC];

    const int t  = threadIdx.x;
    const int tx = t & 15, ty = t >> 4;
    {
        int c = t;
        int g = c / GC;
        float rs = g_rstd[n * NGRP + g];
        float mn = g_mean[n * NGRP + g];
        float s  = rs * norm_w[c];
        sc[c] = s;
        bc[c] = norm_b[c] - mn * s;
    }
    __syncthreads();

    float acc[4][4] = {};
    const float* xb = x + (size_t)n * CC * HWD;

    for (int k0 = 0; k0 < CC; k0 += 16) {
        {
            int m  = t & 63;
            int kb = (t >> 6) * 4;
            float4 a4 = *(const float4*)(qkv_w + (size_t)(o0 + m) * CC + k0 + kb);
            As[kb + 0][m] = a4.x; As[kb + 1][m] = a4.y;
            As[kb + 2][m] = a4.z; As[kb + 3][m] = a4.w;
        }
        {
            int j  = t & 63;
            int kr = t >> 6;
            #pragma unroll
            for (int r = 0; r < 4; r++) {
                int k = kr + r * 4;
                int c = k0 + k;
                Bs[k][j] = xb[(size_t)c * HWD + j0 + j] * sc[c] + bc[c];
            }
        }
        __syncthreads();
        #pragma unroll
        for (int kk = 0; kk < 16; kk++) {
            float4 a4 = *(const float4*)&As[kk][ty * 4];
            float4 b4 = *(const float4*)&Bs[kk][tx * 4];
            float a[4] = {a4.x, a4.y, a4.z, a4.w};
            float b[4] = {b4.x, b4.y, b4.z, b4.w};
            #pragma unroll
            for (int i = 0; i < 4; i++)
                #pragma unroll
                for (int j = 0; j < 4; j++)
                    acc[i][j] += a[i] * b[j];
        }
        __syncthreads();
    }

    #pragma unroll
    for (int i = 0; i < 4; i++) {
        int o    = o0 + ty * 4 + i;
        int part = o >> 8;
        int c    = o & 255;
        float bias  = qkv_b[o];
        float scale = (part == 0) ? (0.125f * LOG2E) : 1.0f;
        __half* dst = (part == 0) ? g_q16 : ((part == 1) ? g_k16 : g_v16);
        size_t idx  = (size_t)n * CC * HWD + (size_t)c * HWD + j0 + tx * 4;
        uint32_t u0 = pack2((acc[i][0] + bias) * scale, (acc[i][1] + bias) * scale);
        uint32_t u1 = pack2((acc[i][2] + bias) * scale, (acc[i][3] + bias) * scale);
        *(uint32_t*)&dst[idx]     = u0;
        *(uint32_t*)&dst[idx + 2] = u1;
    }
}

// ---------------- Flash attention with mma.sync fp16 ----------------
// CTA: 128 queries, 8 warps (16 rows each). K/V streamed 64 keys/chunk,
// double-buffered via cp.async. smem tiles stay [hd][seq]-natural;
// Q/K fragments loaded with ldmatrix.trans, V with ldmatrix.
#define QP 136   // Qs row stride (halves): 272B = 17*16B, conflict-free
#define KP 72    // Ks/Vs row stride (halves): 144B = 9*16B, conflict-free
#define SM_Q  (64 * QP * 2)          // 17408
#define SM_KV (64 * KP * 2)          // 9216 per tensor per buffer
#define SM_TOT (SM_Q + 4 * SM_KV)    // 54272

__global__ __launch_bounds__(256, 1) void attn_kernel() {
    extern __shared__ __align__(16) char smem[];
    __half* Qs = (__half*)smem;                                // [64][QP]
    __half* Ks = (__half*)(smem + SM_Q);                       // [2][64][KP]
    __half* Vs = (__half*)(smem + SM_Q + 2 * SM_KV);           // [2][64][KP]

    const int n = blockIdx.y >> 2, h = blockIdx.y & 3;
    const int q0 = blockIdx.x * 128;
    const size_t base = (size_t)(n * CC + h * HD) * HWD;
    const __half* qg = g_q16 + base;
    const __half* kg = g_k16 + base;
    const __half* vg = g_v16 + base;

    const int tid  = threadIdx.x;
    const int w    = tid >> 5, lane = tid & 31;
    const int g    = lane >> 2, t4 = lane & 3;
    const int mi   = lane >> 3, r8 = lane & 7;

    // stage Q tile [64 hd][128 q]
    #pragma unroll
    for (int i = 0; i < 4; i++) {
        int s = tid + 256 * i;
        int row = s >> 4;
        int c8  = (s & 15) * 8;
        *(uint4*)&Qs[row * QP + c8] = *(const uint4*)&qg[(size_t)row * HWD + q0 + c8];
    }

    // prefetch chunk 0
    {
        #pragma unroll
        for (int i = 0; i < 2; i++) {
            int s = tid + 256 * i;
            int row = s >> 3, c8 = (s & 7) * 8;
            cp16(&Ks[row * KP + c8], &kg[(size_t)row * HWD + c8]);
            cp16(&Vs[row * KP + c8], &vg[(size_t)row * HWD + c8]);
        }
        asm volatile("cp.async.commit_group;\n");
    }
    __syncthreads();

    // A fragments for Q (per warp, 16 rows at q0 + w*16)
    uint32_t aq[4][4];
    #pragma unroll
    for (int kt = 0; kt < 4; kt++) {
        int hd = kt * 16 + (mi >> 1) * 8 + r8;
        int qq = w * 16 + (mi & 1) * 8;
        ldsm4t(aq[kt], &Qs[hd * QP + qq]);
    }

    float o[8][4] = {};
    float mrun0 = -INFINITY, mrun1 = -INFINITY;
    float l0 = 0.f, l1 = 0.f;

    for (int c = 0; c < 64; c++) {
        int buf = c & 1;
        if (c + 1 < 64) {
            int nb = (c + 1) & 1;
            int j0 = (c + 1) * 64;
            #pragma unroll
            for (int i = 0; i < 2; i++) {
                int s = tid + 256 * i;
                int row = s >> 3, c8 = (s & 7) * 8;
                cp16(&Ks[(nb * 64 + row) * KP + c8], &kg[(size_t)row * HWD + j0 + c8]);
                cp16(&Vs[(nb * 64 + row) * KP + c8], &vg[(size_t)row * HWD + j0 + c8]);
            }
            asm volatile("cp.async.commit_group;\n");
            asm volatile("cp.async.wait_group 1;\n");
        } else {
            asm volatile("cp.async.wait_group 0;\n");
        }
        __syncthreads();

        const __half* Kb = &Ks[buf * 64 * KP];
        const __half* Vb = &Vs[buf * 64 * KP];

        // ---- S = Q K^T  (16 x 64 per warp) ----
        float s[8][4] = {};
        #pragma unroll
        for (int kt = 0; kt < 4; kt++) {
            #pragma unroll
            for (int ntp = 0; ntp < 4; ntp++) {
                uint32_t b[4];
                int hd  = kt * 16 + (mi & 1) * 8 + r8;
                int key = ntp * 16 + (mi >> 1) * 8;
                ldsm4t(b, &Kb[hd * KP + key]);
                mma16816(s[2 * ntp],     aq[kt], b[0], b[1]);
                mma16816(s[2 * ntp + 1], aq[kt], b[2], b[3]);
            }
        }

        // ---- online softmax ----
        float mx0 = s[0][0], mx1 = s[0][2];
        #pragma unroll
        for (int nt = 0; nt < 8; nt++) {
            mx0 = fmaxf(mx0, fmaxf(s[nt][0], s[nt][1]));
            mx1 = fmaxf(mx1, fmaxf(s[nt][2], s[nt][3]));
        }
        mx0 = fmaxf(mx0, __shfl_xor_sync(0xffffffffu, mx0, 1));
        mx0 = fmaxf(mx0, __shfl_xor_sync(0xffffffffu, mx0, 2));
        mx1 = fmaxf(mx1, __shfl_xor_sync(0xffffffffu, mx1, 1));
        mx1 = fmaxf(mx1, __shfl_xor_sync(0xffffffffu, mx1, 2));
        float mnew0 = fmaxf(mrun0, mx0), mnew1 = fmaxf(mrun1, mx1);
        float corr0 = ex2(mrun0 - mnew0), corr1 = ex2(mrun1 - mnew1);
        mrun0 = mnew0; mrun1 = mnew1;

        uint32_t phlo[8], phhi[8];
        float ls0 = 0.f, ls1 = 0.f;
        #pragma unroll
        for (int nt = 0; nt < 8; nt++) {
            float p0 = ex2(s[nt][0] - mnew0);
            float p1 = ex2(s[nt][1] - mnew0);
            float p2 = ex2(s[nt][2] - mnew1);
            float p3 = ex2(s[nt][3] - mnew1);
            ls0 += p0 + p1; ls1 += p2 + p3;
            phlo[nt] = pack2(p0, p1);
            phhi[nt] = pack2(p2, p3);
        }
        l0 = l0 * corr0 + ls0;
        l1 = l1 * corr1 + ls1;
        #pragma unroll
        for (int nt = 0; nt < 8; nt++) {
            o[nt][0] *= corr0; o[nt][1] *= corr0;
            o[nt][2] *= corr1; o[nt][3] *= corr1;
        }

        // ---- O += P V ----
        #pragma unroll
        for (int kt = 0; kt < 4; kt++) {
            uint32_t ap[4] = { phlo[2 * kt], phhi[2 * kt], phlo[2 * kt + 1], phhi[2 * kt + 1] };
            #pragma unroll
            for (int ntp = 0; ntp < 4; ntp++) {
                uint32_t b[4];
                int d = ntp * 16 + (mi >> 1) * 8 + r8;
                int j = kt * 16 + (mi & 1) * 8;
                ldsm4(b, &Vb[d * KP + j]);
                mma16816(o[2 * ntp],     ap, b[0], b[1]);
                mma16816(o[2 * ntp + 1], ap, b[2], b[3]);
            }
        }
        __syncthreads();
    }

    // final row-sum reduce + normalize + store
    l0 += __shfl_xor_sync(0xffffffffu, l0, 1);
    l0 += __shfl_xor_sync(0xffffffffu, l0, 2);
    l1 += __shfl_xor_sync(0xffffffffu, l1, 1);
    l1 += __shfl_xor_sync(0xffffffffu, l1, 2);
    float li0 = 1.0f / l0, li1 = 1.0f / l1;

    float* aob = g_ao + base;
    int q = q0 + w * 16 + g;
    #pragma unroll
    for (int nt = 0; nt < 8; nt++) {
        int d = 8 * nt + 2 * t4;
        aob[(size_t)d * HWD + q]           = o[nt][0] * li0;
        aob[(size_t)(d + 1) * HWD + q]     = o[nt][1] * li0;
        aob[(size_t)d * HWD + q + 8]       = o[nt][2] * li1;
        aob[(size_t)(d + 1) * HWD + q + 8] = o[nt][3] * li1;
    }
}

// ---------------- Projection + residual + mask ----------------
__global__ __launch_bounds__(256) void proj_gemm_kernel(
    const float* __restrict__ x, const float* __restrict__ mask,
    const float* __restrict__ pw, const float* __restrict__ pb,
    float* __restrict__ out)
{
    const int n  = blockIdx.z;
    const int o0 = blockIdx.y * 64;
    const int j0 = blockIdx.x * 64;
    __shared__ __align__(16) float As[16][64];
    __shared__ __align__(16) float Bs[16][64];
    const int t  = threadIdx.x;
    const int tx = t & 15, ty = t >> 4;

    float acc[4][4] = {};
    const float* Bb = g_ao + (size_t)n * CC * HWD;

    for (int k0 = 0; k0 < CC; k0 += 16) {
        {
            int m  = t & 63;
            int kb = (t >> 6) * 4;
            float4 a4 = *(const float4*)(pw + (size_t)(o0 + m) * CC + k0 + kb);
            As[kb + 0][m] = a4.x; As[kb + 1][m] = a4.y;
            As[kb + 2][m] = a4.z; As[kb + 3][m] = a4.w;
        }
        {
            int j  = t & 63;
            int kr = t >> 6;
            #pragma unroll
            for (int r = 0; r < 4; r++) {
                int k = kr + r * 4;
                Bs[k][j] = Bb[(size_t)(k0 + k) * HWD + j0 + j];
            }
        }
        __syncthreads();
        #pragma unroll
        for (int kk = 0; kk < 16; kk++) {
            float4 a4 = *(const float4*)&As[kk][ty * 4];
            float4 b4 = *(const float4*)&Bs[kk][tx * 4];
            float a[4] = {a4.x, a4.y, a4.z, a4.w};
            float b[4] = {b4.x, b4.y, b4.z, b4.w};
            #pragma unroll
            for (int i = 0; i < 4; i++)
                #pragma unroll
                for (int j = 0; j < 4; j++)
                    acc[i][j] += a[i] * b[j];
        }
        __syncthreads();
    }

    float4 mv = *(const float4*)(mask + (size_t)n * HWD + j0 + tx * 4);
    #pragma unroll
    for (int i = 0; i < 4; i++) {
        int o = o0 + ty * 4 + i;
        float bias = pb[o];
        size_t off = (size_t)n * CC * HWD + (size_t)o * HWD + j0 + tx * 4;
        float4 xv = *(const float4*)(x + off);
        float4 r;
        r.x = (xv.x + acc[i][0] + bias) * mv.x;
        r.y = (xv.y + acc[i][1] + bias) * mv.y;
        r.z = (xv.z + acc[i][2] + bias) * mv.z;
        r.w = (xv.w + acc[i][3] + bias) * mv.w;
        *(float4*)(out + off) = r;
    }
}

__global__ void copy_mask_kernel(const float* __restrict__ mask, float* __restrict__ out) {
    int i = blockIdx.x * blockDim.x + threadIdx.x;
    if (i < NB * HWD) out[i] = mask[i];
}

// ---------------------------------------------------------------------------
extern "C" void kernel_launch(void* const* d_in, const int* in_sizes, int n_in,
                              void* d_out, int out_size) {
    const float* x      = (const float*)d_in[0];
    const float* mask   = (const float*)d_in[1];
    const float* norm_w = (const float*)d_in[2];
    const float* norm_b = (const float*)d_in[3];
    const float* qkv_w  = (const float*)d_in[4];
    const float* qkv_b  = (const float*)d_in[5];
    const float* proj_w = (const float*)d_in[6];
    const float* proj_b = (const float*)d_in[7];
    float* out = (float*)d_out;

    cudaFuncSetAttribute(attn_kernel, cudaFuncAttributeMaxDynamicSharedMemorySize, SM_TOT);

    gn_part_kernel<<<256, 256>>>(x);
    gn_final_kernel<<<1, 32>>>();
    qkv_gemm_kernel<<<dim3(HWD / 64, (3 * CC) / 64, NB), 256>>>(x, norm_w, norm_b, qkv_w, qkv_b);
    attn_kernel<<<dim3(HWD / 128, NB * NH), 256, SM_TOT>>>();
    proj_gemm_kernel<<<dim3(HWD / 64, CC / 64, NB), 256>>>(x, mask, proj_w, proj_b, out);
    if (out_size >= NB * CC * HWD + NB * HWD)
        copy_mask_kernel<<<(NB * HWD) / 256, 256>>>(mask, out + (size_t)NB * CC * HWD);
}

// round 3
// speedup vs baseline: 9.9410x; 2.0980x over previous
#include <cuda_runtime.h>
#include <cuda_fp16.h>
#include <math.h>
#include <stdint.h>

#define NB 4
#define CC 256
#define HWD 4096
#define NH 4
#define HD 64
#define NGRP 8
#define GC 32
#define EPSV 1e-5f
#define LOG2E 1.44269504088896340736f

// ---- scratch (allocation-free) ----
__device__ __half g_q16[NB * CC * HWD];
__device__ __half g_k16[NB * CC * HWD];
__device__ __half g_v16[NB * CC * HWD];
__device__ __half g_ao16[NB * CC * HWD];
__device__ __half g_xn16[NB * CC * HWD];
__device__ __half g_qw16[3 * CC * CC];
__device__ __half g_pw16[CC * CC];
__device__ float  g_part[256 * 2];
__device__ float  g_mean[NB * NGRP];
__device__ float  g_rstd[NB * NGRP];

// ---------------- helpers ----------------
__device__ __forceinline__ float ex2(float x) {
    float y; asm("ex2.approx.ftz.f32 %0, %1;" : "=f"(y) : "f"(x)); return y;
}
__device__ __forceinline__ uint32_t h2ex2(uint32_t x) {
    uint32_t y; asm("ex2.approx.f16x2 %0, %1;" : "=r"(y) : "r"(x)); return y;
}
__device__ __forceinline__ uint32_t pack2(float a, float b) {
    __half2 h = __floats2half2_rn(a, b);
    return *reinterpret_cast<uint32_t*>(&h);
}
__device__ __forceinline__ uint32_t sptr(const void* p) {
    return (uint32_t)__cvta_generic_to_shared(p);
}
__device__ __forceinline__ void cp16(void* dst, const void* src) {
    asm volatile("cp.async.cg.shared.global [%0], [%1], 16;\n"
                 :: "r"(sptr(dst)), "l"(src));
}
__device__ __forceinline__ void ldsm4t(uint32_t* f, const void* p) {
    asm volatile("ldmatrix.sync.aligned.m8n8.x4.trans.shared.b16 {%0,%1,%2,%3}, [%4];\n"
                 : "=r"(f[0]), "=r"(f[1]), "=r"(f[2]), "=r"(f[3]) : "r"(sptr(p)));
}
__device__ __forceinline__ void ldsm4(uint32_t* f, const void* p) {
    asm volatile("ldmatrix.sync.aligned.m8n8.x4.shared.b16 {%0,%1,%2,%3}, [%4];\n"
                 : "=r"(f[0]), "=r"(f[1]), "=r"(f[2]), "=r"(f[3]) : "r"(sptr(p)));
}
__device__ __forceinline__ void mma16816(float* c, const uint32_t* a, uint32_t b0, uint32_t b1) {
    asm volatile(
        "mma.sync.aligned.m16n8k16.row.col.f32.f16.f16.f32 "
        "{%0,%1,%2,%3}, {%4,%5,%6,%7}, {%8,%9}, {%0,%1,%2,%3};\n"
        : "+f"(c[0]), "+f"(c[1]), "+f"(c[2]), "+f"(c[3])
        : "r"(a[0]), "r"(a[1]), "r"(a[2]), "r"(a[3]), "r"(b0), "r"(b1));
}

// ---------------- GroupNorm stats, 2-stage ----------------
__global__ void gn_part_kernel(const float* __restrict__ x) {
    int ng = blockIdx.x >> 3, part = blockIdx.x & 7;
    const float4* xp = (const float4*)(x + (size_t)ng * GC * HWD);
    float s = 0.f, ss = 0.f;
    int i0 = part * 4096;
    for (int i = i0 + threadIdx.x; i < i0 + 4096; i += 256) {
        float4 v = xp[i];
        s  += v.x + v.y + v.z + v.w;
        ss += v.x * v.x + v.y * v.y + v.z * v.z + v.w * v.w;
    }
    #pragma unroll
    for (int off = 16; off; off >>= 1) {
        s  += __shfl_down_sync(0xffffffffu, s, off);
        ss += __shfl_down_sync(0xffffffffu, ss, off);
    }
    __shared__ float sh[16];
    int w = threadIdx.x >> 5;
    if ((threadIdx.x & 31) == 0) { sh[w] = s; sh[8 + w] = ss; }
    __syncthreads();
    if (threadIdx.x == 0) {
        float S = 0.f, SS = 0.f;
        #pragma unroll
        for (int i = 0; i < 8; i++) { S += sh[i]; SS += sh[8 + i]; }
        g_part[blockIdx.x * 2] = S; g_part[blockIdx.x * 2 + 1] = SS;
    }
}
__global__ void gn_final_kernel() {
    int ng = threadIdx.x;
    if (ng < NB * NGRP) {
        float s = 0.f, ss = 0.f;
        #pragma unroll
        for (int p = 0; p < 8; p++) {
            s  += g_part[(ng * 8 + p) * 2];
            ss += g_part[(ng * 8 + p) * 2 + 1];
        }
        const float inv = 1.0f / (float)(GC * HWD);
        float m = s * inv;
        g_mean[ng] = m;
        g_rstd[ng] = rsqrtf(ss * inv - m * m + EPSV);
    }
}

// ---------------- normalize x -> fp16 [c][hw] ----------------
__global__ void prep_xn_kernel(const float* __restrict__ x,
                               const float* __restrict__ nw, const float* __restrict__ nb_) {
    int row = blockIdx.x;               // n*CC + c
    int n = row >> 8, c = row & 255;
    int grp = c / GC;
    float rs = g_rstd[n * NGRP + grp], m = g_mean[n * NGRP + grp];
    float scv = rs * nw[c];
    float bcv = nb_[c] - m * scv;
    const float4* xp = (const float4*)(x + (size_t)row * HWD);
    __half* dst = g_xn16 + (size_t)row * HWD;
    #pragma unroll
    for (int i = 0; i < 4; i++) {
        int idx = threadIdx.x + 256 * i;
        float4 v = xp[idx];
        uint2 u;
        u.x = pack2(v.x * scv + bcv, v.y * scv + bcv);
        u.y = pack2(v.z * scv + bcv, v.w * scv + bcv);
        *(uint2*)&dst[idx * 4] = u;
    }
}

// ---------------- weights -> fp16 ----------------
__global__ void conv_w_kernel(const float* __restrict__ qw, const float* __restrict__ pw) {
    int i = blockIdx.x * 256 + threadIdx.x;
    if (i < 3 * CC * CC) g_qw16[i] = __float2half(qw[i]);
    if (i < CC * CC)     g_pw16[i] = __float2half(pw[i]);
}

// ---------------- fp16 tensor-core GEMM: QKV ----------------
// C[o][j] = sum_k W[o][k] * xn[k][j]; CTA 128x128, K-chunk 32, 8 warps 32x64.
__global__ __launch_bounds__(256, 2) void gemm_qkv16_kernel(const float* __restrict__ qkv_b) {
    const int n  = blockIdx.z;
    const int o0 = blockIdx.y * 128;
    const int j0 = blockIdx.x * 128;
    __shared__ __align__(16) __half As[2][128][40];
    __shared__ __align__(16) __half Bs[2][32][136];

    const int tid = threadIdx.x, w = tid >> 5, lane = tid & 31;
    const int wm = w >> 1, wn = w & 1;
    const int g = lane >> 2, t4 = lane & 3, mi = lane >> 3, r8 = lane & 7;
    const int la = lane & 15, ha = lane >> 4;
    const __half* xn = g_xn16 + (size_t)n * CC * HWD;

    auto prefetch = [&](int buf, int k0) {
        #pragma unroll
        for (int i = 0; i < 2; i++) {
            int s = tid + 256 * i;
            int row = s >> 2, c8 = (s & 3) * 8;
            cp16(&As[buf][row][c8], &g_qw16[(size_t)(o0 + row) * CC + k0 + c8]);
        }
        #pragma unroll
        for (int i = 0; i < 2; i++) {
            int s = tid + 256 * i;
            int row = s >> 4, c8 = (s & 15) * 8;
            cp16(&Bs[buf][row][c8], &xn[(size_t)(k0 + row) * HWD + j0 + c8]);
        }
        asm volatile("cp.async.commit_group;\n");
    };

    float acc[2][8][4] = {};
    prefetch(0, 0);
    for (int c = 0; c < 8; c++) {
        int buf = c & 1;
        if (c + 1 < 8) { prefetch(buf ^ 1, (c + 1) * 32); asm volatile("cp.async.wait_group 1;\n"); }
        else           { asm volatile("cp.async.wait_group 0;\n"); }
        __syncthreads();
        #pragma unroll
        for (int ks = 0; ks < 2; ks++) {
            uint32_t a[2][4];
            #pragma unroll
            for (int mt = 0; mt < 2; mt++)
                ldsm4(a[mt], &As[buf][wm * 32 + mt * 16 + la][ks * 16 + ha * 8]);
            #pragma unroll
            for (int nb = 0; nb < 4; nb++) {
                uint32_t b[4];
                ldsm4t(b, &Bs[buf][ks * 16 + (mi & 1) * 8 + r8][wn * 64 + nb * 16 + (mi >> 1) * 8]);
                #pragma unroll
                for (int mt = 0; mt < 2; mt++) {
                    mma16816(acc[mt][2 * nb],     a[mt], b[0], b[1]);
                    mma16816(acc[mt][2 * nb + 1], a[mt], b[2], b[3]);
                }
            }
        }
        __syncthreads();
    }

    const int part = o0 >> 8;
    __half* dst = (part == 0) ? g_q16 : ((part == 1) ? g_k16 : g_v16);
    const float scale = (part == 0) ? (0.125f * LOG2E) : 1.0f;
    #pragma unroll
    for (int mt = 0; mt < 2; mt++) {
        int o_lo = o0 + wm * 32 + mt * 16 + g;
        float b_lo = qkv_b[o_lo], b_hi = qkv_b[o_lo + 8];
        int c_lo = o_lo & 255;
        #pragma unroll
        for (int nt = 0; nt < 8; nt++) {
            int j = j0 + wn * 64 + nt * 8 + 2 * t4;
            *(uint32_t*)&dst[((size_t)n * CC + c_lo) * HWD + j] =
                pack2((acc[mt][nt][0] + b_lo) * scale, (acc[mt][nt][1] + b_lo) * scale);
            *(uint32_t*)&dst[((size_t)n * CC + c_lo + 8) * HWD + j] =
                pack2((acc[mt][nt][2] + b_hi) * scale, (acc[mt][nt][3] + b_hi) * scale);
        }
    }
}

// ---------------- fp16 tensor-core GEMM: proj + residual + mask ----------------
__global__ __launch_bounds__(256, 2) void gemm_proj16_kernel(
    const float* __restrict__ x, const float* __restrict__ mask,
    const float* __restrict__ pb, float* __restrict__ out)
{
    const int n  = blockIdx.z;
    const int o0 = blockIdx.y * 128;
    const int j0 = blockIdx.x * 128;
    __shared__ __align__(16) __half As[2][128][40];
    __shared__ __align__(16) __half Bs[2][32][136];

    const int tid = threadIdx.x, w = tid >> 5, lane = tid & 31;
    const int wm = w >> 1, wn = w & 1;
    const int g = lane >> 2, t4 = lane & 3, mi = lane >> 3, r8 = lane & 7;
    const int la = lane & 15, ha = lane >> 4;
    const __half* Bsrc = g_ao16 + (size_t)n * CC * HWD;

    auto prefetch = [&](int buf, int k0) {
        #pragma unroll
        for (int i = 0; i < 2; i++) {
            int s = tid + 256 * i;
            int row = s >> 2, c8 = (s & 3) * 8;
            cp16(&As[buf][row][c8], &g_pw16[(size_t)(o0 + row) * CC + k0 + c8]);
        }
        #pragma unroll
        for (int i = 0; i < 2; i++) {
            int s = tid + 256 * i;
            int row = s >> 4, c8 = (s & 15) * 8;
            cp16(&Bs[buf][row][c8], &Bsrc[(size_t)(k0 + row) * HWD + j0 + c8]);
        }
        asm volatile("cp.async.commit_group;\n");
    };

    float acc[2][8][4] = {};
    prefetch(0, 0);
    for (int c = 0; c < 8; c++) {
        int buf = c & 1;
        if (c + 1 < 8) { prefetch(buf ^ 1, (c + 1) * 32); asm volatile("cp.async.wait_group 1;\n"); }
        else           { asm volatile("cp.async.wait_group 0;\n"); }
        __syncthreads();
        #pragma unroll
        for (int ks = 0; ks < 2; ks++) {
            uint32_t a[2][4];
            #pragma unroll
            for (int mt = 0; mt < 2; mt++)
                ldsm4(a[mt], &As[buf][wm * 32 + mt * 16 + la][ks * 16 + ha * 8]);
            #pragma unroll
            for (int nb = 0; nb < 4; nb++) {
                uint32_t b[4];
                ldsm4t(b, &Bs[buf][ks * 16 + (mi & 1) * 8 + r8][wn * 64 + nb * 16 + (mi >> 1) * 8]);
                #pragma unroll
                for (int mt = 0; mt < 2; mt++) {
                    mma16816(acc[mt][2 * nb],     a[mt], b[0], b[1]);
                    mma16816(acc[mt][2 * nb + 1], a[mt], b[2], b[3]);
                }
            }
        }
        __syncthreads();
    }

    #pragma unroll
    for (int mt = 0; mt < 2; mt++) {
        int o_lo = o0 + wm * 32 + mt * 16 + g;
        float b_lo = pb[o_lo], b_hi = pb[o_lo + 8];
        #pragma unroll
        for (int nt = 0; nt < 8; nt++) {
            int j = j0 + wn * 64 + nt * 8 + 2 * t4;
            float2 mv = *(const float2*)&mask[(size_t)n * HWD + j];
            size_t off = ((size_t)n * CC + o_lo) * HWD + j;
            float2 xv = *(const float2*)&x[off];
            float2 r;
            r.x = (xv.x + acc[mt][nt][0] + b_lo) * mv.x;
            r.y = (xv.y + acc[mt][nt][1] + b_lo) * mv.y;
            *(float2*)&out[off] = r;
            size_t off2 = off + 8 * HWD;
            float2 xv2 = *(const float2*)&x[off2];
            float2 r2;
            r2.x = (xv2.x + acc[mt][nt][2] + b_hi) * mv.x;
            r2.y = (xv2.y + acc[mt][nt][3] + b_hi) * mv.y;
            *(float2*)&out[off2] = r2;
        }
    }
}

// ---------------- Flash attention: 4 warps, 32 q-rows/warp ----------------
#define KP 72
#define QP 136
__global__ __launch_bounds__(128, 2) void attn_kernel() {
    __shared__ __align__(16) __half SMh[18432];   // 36864 B
    const int n = blockIdx.y >> 2, h = blockIdx.y & 3;
    const int q0 = blockIdx.x * 128;
    const size_t base = (size_t)(n * CC + h * HD) * HWD;
    const __half* qg = g_q16 + base;
    const __half* kg = g_k16 + base;
    const __half* vg = g_v16 + base;

    const int tid = threadIdx.x, w = tid >> 5, lane = tid & 31;
    const int g = lane >> 2, t4 = lane & 3, mi = lane >> 3, r8 = lane & 7;

    // stage Q [64 hd][128 q] into smem (region reused by K/V buffers later)
    #pragma unroll
    for (int i = 0; i < 8; i++) {
        int s = tid + 128 * i;
        int row = s >> 4, c8 = (s & 15) * 8;
        *(uint4*)&SMh[row * QP + c8] = *(const uint4*)&qg[(size_t)row * HWD + q0 + c8];
    }
    __syncthreads();
    uint32_t aq[2][4][4];
    #pragma unroll
    for (int mt = 0; mt < 2; mt++)
        #pragma unroll
        for (int kt = 0; kt < 4; kt++)
            ldsm4t(aq[mt][kt],
                   &SMh[(kt * 16 + (mi >> 1) * 8 + r8) * QP + w * 32 + mt * 16 + (mi & 1) * 8]);
    __syncthreads();

    auto prefetch = [&](int buf, int c) {
        int jc = c * 64;
        __half* Kb = &SMh[buf * 4608];
        __half* Vb = &SMh[9216 + buf * 4608];
        #pragma unroll
        for (int i = 0; i < 4; i++) {
            int s = tid + 128 * i;
            int row = s >> 3, c8 = (s & 7) * 8;
            cp16(&Kb[row * KP + c8], &kg[(size_t)row * HWD + jc + c8]);
            cp16(&Vb[row * KP + c8], &vg[(size_t)row * HWD + jc + c8]);
        }
        asm volatile("cp.async.commit_group;\n");
    };

    float o_[2][8][4] = {};
    float mrun[2][2] = {{-INFINITY, -INFINITY}, {-INFINITY, -INFINITY}};
    float l[2][2] = {};

    prefetch(0, 0);
    for (int c = 0; c < 64; c++) {
        int buf = c & 1;
        if (c + 1 < 64) { prefetch(buf ^ 1, c + 1); asm volatile("cp.async.wait_group 1;\n"); }
        else            { asm volatile("cp.async.wait_group 0;\n"); }
        __syncthreads();
        const __half* Kb = &SMh[buf * 4608];
        const __half* Vb = &SMh[9216 + buf * 4608];

        // S = Q K^T  (32q x 64keys per warp)
        float s[2][8][4] = {};
        #pragma unroll
        for (int kt = 0; kt < 4; kt++) {
            #pragma unroll
            for (int ntp = 0; ntp < 4; ntp++) {
                uint32_t b[4];
                ldsm4t(b, &Kb[(kt * 16 + (mi & 1) * 8 + r8) * KP + ntp * 16 + (mi >> 1) * 8]);
                #pragma unroll
                for (int mt = 0; mt < 2; mt++) {
                    mma16816(s[mt][2 * ntp],     aq[mt][kt], b[0], b[1]);
                    mma16816(s[mt][2 * ntp + 1], aq[mt][kt], b[2], b[3]);
                }
            }
        }

        // online softmax (per m-tile, two row-halves)
        uint32_t ph[2][8], phh[2][8];
        #pragma unroll
        for (int mt = 0; mt < 2; mt++) {
            float mx0 = -INFINITY, mx1 = -INFINITY;
            #pragma unroll
            for (int nt = 0; nt < 8; nt++) {
                mx0 = fmaxf(mx0, fmaxf(s[mt][nt][0], s[mt][nt][1]));
                mx1 = fmaxf(mx1, fmaxf(s[mt][nt][2], s[mt][nt][3]));
            }
            mx0 = fmaxf(mx0, __shfl_xor_sync(0xffffffffu, mx0, 1));
            mx0 = fmaxf(mx0, __shfl_xor_sync(0xffffffffu, mx0, 2));
            mx1 = fmaxf(mx1, __shfl_xor_sync(0xffffffffu, mx1, 1));
            mx1 = fmaxf(mx1, __shfl_xor_sync(0xffffffffu, mx1, 2));
            float mnew0 = fmaxf(mrun[mt][0], mx0), mnew1 = fmaxf(mrun[mt][1], mx1);
            float corr0 = ex2(mrun[mt][0] - mnew0), corr1 = ex2(mrun[mt][1] - mnew1);
            mrun[mt][0] = mnew0; mrun[mt][1] = mnew1;

            __half2 hs0 = __floats2half2_rn(0.f, 0.f), hs1 = hs0;
            #pragma unroll
            for (int nt = 0; nt < 8; nt++) {
                ph[mt][nt]  = h2ex2(pack2(s[mt][nt][0] - mnew0, s[mt][nt][1] - mnew0));
                phh[mt][nt] = h2ex2(pack2(s[mt][nt][2] - mnew1, s[mt][nt][3] - mnew1));
                hs0 = __hadd2(hs0, *(__half2*)&ph[mt][nt]);
                hs1 = __hadd2(hs1, *(__half2*)&phh[mt][nt]);
            }
            l[mt][0] = l[mt][0] * corr0 + __low2float(hs0) + __high2float(hs0);
            l[mt][1] = l[mt][1] * corr1 + __low2float(hs1) + __high2float(hs1);
            #pragma unroll
            for (int nt = 0; nt < 8; nt++) {
                o_[mt][nt][0] *= corr0; o_[mt][nt][1] *= corr0;
                o_[mt][nt][2] *= corr1; o_[mt][nt][3] *= corr1;
            }
        }

        // O += P V
        #pragma unroll
        for (int kt = 0; kt < 4; kt++) {
            #pragma unroll
            for (int ntp = 0; ntp < 4; ntp++) {
                uint32_t b[4];
                ldsm4(b, &Vb[(ntp * 16 + (mi >> 1) * 8 + r8) * KP + kt * 16 + (mi & 1) * 8]);
                #pragma unroll
                for (int mt = 0; mt < 2; mt++) {
                    uint32_t ap[4] = { ph[mt][2 * kt], phh[mt][2 * kt],
                                       ph[mt][2 * kt + 1], phh[mt][2 * kt + 1] };
                    mma16816(o_[mt][2 * ntp],     ap, b[0], b[1]);
                    mma16816(o_[mt][2 * ntp + 1], ap, b[2], b[3]);
                }
            }
        }
        __syncthreads();
    }

    // finalize: row sums across quad, normalize, stage [q][d] in smem, transpose out
    #pragma unroll
    for (int mt = 0; mt < 2; mt++)
        #pragma unroll
        for (int hh = 0; hh < 2; hh++) {
            l[mt][hh] += __shfl_xor_sync(0xffffffffu, l[mt][hh], 1);
            l[mt][hh] += __shfl_xor_sync(0xffffffffu, l[mt][hh], 2);
        }
    #pragma unroll
    for (int mt = 0; mt < 2; mt++) {
        float li0 = 1.0f / l[mt][0], li1 = 1.0f / l[mt][1];
        int qr = w * 32 + mt * 16 + g;
        #pragma unroll
        for (int nt = 0; nt < 8; nt++) {
            int d0 = nt * 8 + 2 * t4;
            *(uint32_t*)&SMh[qr * KP + d0]       = pack2(o_[mt][nt][0] * li0, o_[mt][nt][1] * li0);
            *(uint32_t*)&SMh[(qr + 8) * KP + d0] = pack2(o_[mt][nt][2] * li1, o_[mt][nt][3] * li1);
        }
    }
    __syncthreads();
    __half* aob = g_ao16 + base;
    #pragma unroll
    for (int i = 0; i < 32; i++) {
        int f = tid + 128 * i;
        int qp = f & 63, d = f >> 6;
        __half2 hv = __halves2half2(SMh[(2 * qp) * KP + d], SMh[(2 * qp + 1) * KP + d]);
        *(uint32_t*)&aob[(size_t)d * HWD + q0 + 2 * qp] = *(uint32_t*)&hv;
    }
}

__global__ void copy_mask_kernel(const float* __restrict__ mask, float* __restrict__ out) {
    int i = blockIdx.x * blockDim.x + threadIdx.x;
    if (i < NB * HWD) out[i] = mask[i];
}

// ---------------------------------------------------------------------------
extern "C" void kernel_launch(void* const* d_in, const int* in_sizes, int n_in,
                              void* d_out, int out_size) {
    const float* x      = (const float*)d_in[0];
    const float* mask   = (const float*)d_in[1];
    const float* norm_w = (const float*)d_in[2];
    const float* norm_b = (const float*)d_in[3];
    const float* qkv_w  = (const float*)d_in[4];
    const float* qkv_b  = (const float*)d_in[5];
    const float* proj_w = (const float*)d_in[6];
    const float* proj_b = (const float*)d_in[7];
    float* out = (float*)d_out;

    gn_part_kernel<<<256, 256>>>(x);
    conv_w_kernel<<<768, 256>>>(qkv_w, proj_w);
    gn_final_kernel<<<1, 32>>>();
    prep_xn_kernel<<<NB * CC, 256>>>(x, norm_w, norm_b);
    gemm_qkv16_kernel<<<dim3(HWD / 128, (3 * CC) / 128, NB), 256>>>(qkv_b);
    attn_kernel<<<dim3(HWD / 128, NB * NH), 128>>>();
    gemm_proj16_kernel<<<dim3(HWD / 128, CC / 128, NB), 256>>>(x, mask, proj_b, out);
    if (out_size >= NB * CC * HWD + NB * HWD)
        copy_mask_kernel<<<(NB * HWD) / 256, 256>>>(mask, out + (size_t)NB * CC * HWD);
}